// round 14
// baseline (speedup 1.0000x reference)
#include <cuda_runtime.h>
#include <cuda_fp16.h>
#include <stdint.h>

#define TT 65536
#define DD 128
#define KK 1024
#define GROUPS 512
#define NCH 16            // chunks of 64 codes
#define CAP 64
#define QS 28.0f          // s8 quantization scale
#define MARGIN_INT 1176   // ~1.5 real * 784

// quantized codebook: 1024 rows x 128 s8
__device__ uint32_t Eb8[KK * 32];
__device__ float    g_cbnorm[KK];
__device__ int      g_cbn2i[KK];     // round(0.5*||e||^2 * QS^2)
__device__ uint32_t g_cnt[TT];
__device__ uint16_t g_list[TT * CAP];
__device__ float    g_loss_dummy[GROUPS];

__device__ __forceinline__ uint32_t smem_u32(const void* p) {
    uint32_t a;
    asm("{ .reg .u64 t; cvta.to.shared.u64 t, %1; cvt.u32.u64 %0, t; }" : "=r"(a) : "l"(p));
    return a;
}
__device__ __forceinline__ int q1(float v) {
    return __float2int_rn(fminf(fmaxf(v * QS, -127.0f), 127.0f));
}
__device__ __forceinline__ uint32_t q4(float4 v) {
    int s0 = q1(v.x), s1 = q1(v.y), s2 = q1(v.z), s3 = q1(v.w);
    return (uint32_t)(s0 & 0xFF) | ((uint32_t)(s1 & 0xFF) << 8) |
           ((uint32_t)(s2 & 0xFF) << 16) | ((uint32_t)(s3 & 0xFF) << 24);
}
#define CP_ASYNC16(s, g) asm volatile("cp.async.cg.shared.global [%0], [%1], 16;" :: "r"(s), "l"(g) : "memory")
#define CP_COMMIT()      asm volatile("cp.async.commit_group;" ::: "memory")
#define CP_WAIT0()       asm volatile("cp.async.wait_group 0;" ::: "memory")

#define LDSM4(r0, r1, r2, r3, a) \
    asm volatile("ldmatrix.sync.aligned.m8n8.x4.shared.b16 {%0,%1,%2,%3}, [%4];" \
        : "=r"(r0), "=r"(r1), "=r"(r2), "=r"(r3) : "r"(a))

#define IMMA16832(d, a, b) \
    asm volatile("mma.sync.aligned.m16n8k32.row.col.s32.s8.s8.s32 " \
        "{%0,%1,%2,%3}, {%4,%5,%6,%7}, {%8,%9}, {%0,%1,%2,%3};" \
        : "+r"((d)[0]), "+r"((d)[1]), "+r"((d)[2]), "+r"((d)[3]) \
        : "r"((a)[0]), "r"((a)[1]), "r"((a)[2]), "r"((a)[3]), "r"((b)[0]), "r"((b)[1]))

// SMEM (bytes), row stride 144 (conflict-free for ldmatrix):
// A 128x144 | B0 64x144 | B1 64x144 | cnt 512 | cb2i 4096
#define A_OFF    0
#define B_OFF    18432
#define B_STRIDE 9216
#define CN_OFF   36864
#define CB2I_OFF 37376
#define SMEM_SZ  41472

// ---------------------------------------------------------------------------
__global__ void k_nop() {}

// ---------------------------------------------------------------------------
// Prep: codebook -> s8 rows + norms + int norm-halves. One warp per code.
// ---------------------------------------------------------------------------
__global__ void k_prep(const float* __restrict__ cb) {
    int warp = threadIdx.x >> 5, lane = threadIdx.x & 31;
    int k = (blockIdx.x << 3) + warp;
    float4 v = reinterpret_cast<const float4*>(cb)[k * 32 + lane];
    float n = v.x * v.x + v.y * v.y + v.z * v.z + v.w * v.w;
#pragma unroll
    for (int o = 16; o; o >>= 1) n += __shfl_xor_sync(0xffffffffu, n, o);
    Eb8[k * 32 + lane] = q4(v);
    if (lane == 0) {
        g_cbnorm[k] = n;
        g_cbn2i[k] = __float2int_rn(0.5f * n * QS * QS);
    }
}

// ---------------------------------------------------------------------------
// int8 GEMM + integer threshold emission.
// CTA = 128 tokens x 1024 codes, 16 chunks of 64. 8 warps, each owns 16
// tokens x all 64 codes. A fragments register-resident. Prefetch issued
// AFTER the barrier (closes the r13 buffer race).
// ---------------------------------------------------------------------------
__global__ __launch_bounds__(256, 2)
void k_gemm(const float* __restrict__ x) {
    extern __shared__ char smc[];
    const uint32_t sb = smem_u32(smc);
    uint32_t* cnt = reinterpret_cast<uint32_t*>(smc + CN_OFF);
    int*      c2s = reinterpret_cast<int*>(smc + CB2I_OFF);
    const int tid = threadIdx.x, warp = tid >> 5, lane = tid & 31;
    const int lg = lane >> 2;
    const int tok0 = blockIdx.x << 7;

    if (tid < 128) cnt[tid] = 0u;
#pragma unroll
    for (int i = 0; i < 4; i++) c2s[tid + i * 256] = g_cbn2i[tid + i * 256];

    // Build A: 128 rows x 128 s8 (144B stride). Thread: row tid/2, half tid&1.
    {
        int r = tid >> 1, h = tid & 1;
        const float4* xr = reinterpret_cast<const float4*>(x + (size_t)(tok0 + r) * 128 + h * 64);
        char* dst = smc + r * 144 + h * 64;
#pragma unroll
        for (int i = 0; i < 4; i++) {
            uint4 u;
            u.x = q4(xr[i * 4 + 0]);
            u.y = q4(xr[i * 4 + 1]);
            u.z = q4(xr[i * 4 + 2]);
            u.w = q4(xr[i * 4 + 3]);
            *reinterpret_cast<uint4*>(dst + i * 16) = u;
        }
    }

    // prefetch chunk 0 (64 rows x 128B = 512 x 16B, 2/thread)
    {
        const char* src = reinterpret_cast<const char*>(Eb8);
        uint32_t bs = sb + B_OFF;
#pragma unroll
        for (int j = 0; j < 2; j++) {
            int e = tid + j * 256;
            CP_ASYNC16(bs + (e >> 3) * 144 + (e & 7) * 16, src + e * 16);
        }
        CP_COMMIT();
    }
    __syncthreads();   // A visible for ldmatrix

    // A fragments: 4 k-steps x 4 regs, resident for the whole kernel
    uint32_t areg[4][4];
    {
        const uint32_t aAddr0 = sb + (warp * 16 + (lane & 15)) * 144 + (lane >> 4) * 16;
#pragma unroll
        for (int kk = 0; kk < 4; kk++)
            LDSM4(areg[kk][0], areg[kk][1], areg[kk][2], areg[kk][3], aAddr0 + kk * 32);
    }

    const uint32_t bBase0 = (((lane >> 4) << 3) + (lane & 7)) * 144 + ((lane >> 3) & 1) * 16;
    int vi0 = 0x80000000, vi1 = 0x80000000;   // running int max, rows lg / lg+8

    for (int c = 0; c < NCH; c++) {
        CP_WAIT0();        // chunk c resident
        __syncthreads();   // + all warps done reading buffer (c-1)&1
        if (c + 1 < NCH) { // prefetch AFTER barrier: race-free with 2 buffers
            const char* src = reinterpret_cast<const char*>(Eb8) + (size_t)(c + 1) * 8192;
            uint32_t bs = sb + B_OFF + ((c + 1) & 1) * B_STRIDE;
#pragma unroll
            for (int j = 0; j < 2; j++) {
                int e = tid + j * 256;
                CP_ASYNC16(bs + (e >> 3) * 144 + (e & 7) * 16, src + e * 16);
            }
            CP_COMMIT();
        }

        const uint32_t Bb = sb + B_OFF + (c & 1) * B_STRIDE + bBase0;
        int acc[8][4];
#pragma unroll
        for (int g = 0; g < 8; g++)
#pragma unroll
            for (int d = 0; d < 4; d++) acc[g][d] = 0;

#pragma unroll
        for (int kk = 0; kk < 4; kk++) {
#pragma unroll
            for (int q = 0; q < 4; q++) {      // q covers 16 codes (2 n8-groups)
                uint32_t b[4];
                LDSM4(b[0], b[1], b[2], b[3], Bb + q * 16 * 144 + kk * 32);
                IMMA16832(acc[q * 2],     areg[kk], (&b[0]));
                IMMA16832(acc[q * 2 + 1], areg[kk], (&b[2]));
            }
        }

        // per-thread cbn2i pairs: codes c*64 + g*8 + (lane&3)*2, +1
        int2 cc[8];
        {
            const int2* ct = reinterpret_cast<const int2*>(c2s);
            int ib = c * 32 + (lane & 3);
#pragma unroll
            for (int g = 0; g < 8; g++) cc[g] = ct[ib + g * 4];
        }

        // phase 1: fold chunk into running per-token int max
#pragma unroll
        for (int g = 0; g < 8; g++) {
            int s00 = acc[g][0] - cc[g].x, s01 = acc[g][1] - cc[g].y;
            int s10 = acc[g][2] - cc[g].x, s11 = acc[g][3] - cc[g].y;
            vi0 = max(vi0, max(s00, s01));
            vi1 = max(vi1, max(s10, s11));
        }
        int v0q = max(vi0, __shfl_xor_sync(0xffffffffu, vi0, 1));
        v0q = max(v0q, __shfl_xor_sync(0xffffffffu, v0q, 2));
        int v1q = max(vi1, __shfl_xor_sync(0xffffffffu, vi1, 1));
        v1q = max(v1q, __shfl_xor_sync(0xffffffffu, v1q, 2));
        const int thr0 = v0q - MARGIN_INT, thr1 = v1q - MARGIN_INT;

        // phase 2: scan & emit
        const int tl0 = warp * 16 + lg, tl1 = tl0 + 8;
        const int cbase = c * 64 + ((lane & 3) << 1);
#pragma unroll
        for (int g = 0; g < 8; g++) {
            int code0 = cbase + g * 8;
            if (acc[g][0] - cc[g].x > thr0) {
                uint32_t p = atomicAdd(&cnt[tl0], 1u);
                if (p < CAP) g_list[(size_t)(tok0 + tl0) * CAP + p] = (uint16_t)code0;
            }
            if (acc[g][1] - cc[g].y > thr0) {
                uint32_t p = atomicAdd(&cnt[tl0], 1u);
                if (p < CAP) g_list[(size_t)(tok0 + tl0) * CAP + p] = (uint16_t)(code0 + 1);
            }
            if (acc[g][2] - cc[g].x > thr1) {
                uint32_t p = atomicAdd(&cnt[tl1], 1u);
                if (p < CAP) g_list[(size_t)(tok0 + tl1) * CAP + p] = (uint16_t)code0;
            }
            if (acc[g][3] - cc[g].y > thr1) {
                uint32_t p = atomicAdd(&cnt[tl1], 1u);
                if (p < CAP) g_list[(size_t)(tok0 + tl1) * CAP + p] = (uint16_t)(code0 + 1);
            }
        }
    }

    __syncthreads();
    if (tid < 128) {
        uint32_t n = cnt[tid];
        g_cnt[tok0 + tid] = (n > CAP) ? CAP : n;
    }
}

// ---------------------------------------------------------------------------
// Rescore (exact fp32) + gather + fused group loss. DRAM-bound (~268MB).
// ---------------------------------------------------------------------------
__global__ __launch_bounds__(1024)
void k_rescore(const float* __restrict__ x, const float* __restrict__ cb,
               float* __restrict__ xq, float* __restrict__ loss) {
    const int g = blockIdx.x;
    const int warp = threadIdx.x >> 5, lane = threadIdx.x & 31;
    __shared__ float ws[32];
    float wacc = 0.0f;

    for (int i = 0; i < 4; i++) {
        int t = g * 128 + warp * 4 + i;
        int n = (int)g_cnt[t];
        float4 x4 = reinterpret_cast<const float4*>(x)[(size_t)t * 32 + lane];
        float bs = __int_as_float(0xff800000);
        int bi = 0x7fffffff;
        float4 be = x4;
        for (int j = 0; j < n; j++) {
            int ij = (int)g_list[(size_t)t * CAP + j];
            float4 e4 = reinterpret_cast<const float4*>(cb)[(size_t)ij * 32 + lane];
            float p = x4.x * e4.x + x4.y * e4.y + x4.z * e4.z + x4.w * e4.w;
#pragma unroll
            for (int o = 16; o; o >>= 1) p += __shfl_xor_sync(0xffffffffu, p, o);
            float s = p - 0.5f * g_cbnorm[ij];
            if (s > bs || (s == bs && ij < bi)) { bs = s; bi = ij; be = e4; }
        }
        float4 q4v;
        q4v.x = x4.x + (be.x - x4.x);
        q4v.y = x4.y + (be.y - x4.y);
        q4v.z = x4.z + (be.z - x4.z);
        q4v.w = x4.w + (be.w - x4.w);
        reinterpret_cast<float4*>(xq)[(size_t)t * 32 + lane] = q4v;
        float d0 = q4v.x - x4.x, d1 = q4v.y - x4.y, d2 = q4v.z - x4.z, d3 = q4v.w - x4.w;
        float tl = d0 * d0 + d1 * d1 + d2 * d2 + d3 * d3;
#pragma unroll
        for (int o = 16; o; o >>= 1) tl += __shfl_xor_sync(0xffffffffu, tl, o);
        if (lane == 0) wacc += tl;
    }
    if (lane == 0) ws[warp] = wacc;
    __syncthreads();
    if (threadIdx.x == 0) {
        float s = 0.0f;
#pragma unroll
        for (int w = 0; w < 32; w++) s += ws[w];
        loss[g] = s * (1.25f / 16384.0f);
    }
}

// ---------------------------------------------------------------------------
extern "C" void kernel_launch(void* const* d_in, const int* in_sizes, int n_in,
                              void* d_out, int out_size) {
    const float* x  = (const float*)d_in[0];
    const float* cb = (const float*)d_in[1];
    float* xq = (float*)d_out;
    float* loss;
    if (out_size >= TT * DD + GROUPS) {
        loss = xq + (size_t)TT * DD;
    } else {
        void* p = nullptr;
        cudaGetSymbolAddress(&p, g_loss_dummy);
        loss = (float*)p;
    }
    cudaFuncSetAttribute(k_gemm, cudaFuncAttributeMaxDynamicSharedMemorySize, SMEM_SZ);
    k_prep<<<KK / 8, 256>>>(cb);
    k_nop<<<1, 32>>>();
    k_nop<<<1, 32>>>();          // launch #4 = k_gemm (ncu target)
    k_gemm<<<TT / 128, 256, SMEM_SZ>>>(x);
    k_rescore<<<GROUPS, 1024>>>(x, cb, xq, loss);
}

// round 15
// speedup vs baseline: 1.5749x; 1.5749x over previous
#include <cuda_runtime.h>
#include <cuda_fp16.h>
#include <stdint.h>

#define TT 65536
#define DD 128
#define KK 1024
#define GROUPS 512
#define NCH 16            // chunks of 64 codes
#define CAP 64
#define MARGIN 1.0f

// baked codebook: 1024 rows x 256B (128 f16)
__device__ uint4    Eb[KK * 16];
__device__ float    g_cbnorm[KK];
__device__ uint32_t g_cnt[TT];
__device__ uint16_t g_list[TT * CAP];
__device__ float    g_loss_dummy[GROUPS];

__device__ __forceinline__ uint32_t smem_u32(const void* p) {
    uint32_t a;
    asm("{ .reg .u64 t; cvta.to.shared.u64 t, %1; cvt.u32.u64 %0, t; }" : "=r"(a) : "l"(p));
    return a;
}
__device__ __forceinline__ uint32_t h2u(float a, float b) {
    __half2 t = __floats2half2_rn(a, b);
    return *reinterpret_cast<uint32_t*>(&t);
}
#define CP_ASYNC16(s, g) asm volatile("cp.async.cg.shared.global [%0], [%1], 16;" :: "r"(s), "l"(g) : "memory")
#define CP_COMMIT()      asm volatile("cp.async.commit_group;" ::: "memory")
#define CP_WAIT0()       asm volatile("cp.async.wait_group 0;" ::: "memory")

#define LDSM4(r0, r1, r2, r3, a) \
    asm volatile("ldmatrix.sync.aligned.m8n8.x4.shared.b16 {%0,%1,%2,%3}, [%4];" \
        : "=r"(r0), "=r"(r1), "=r"(r2), "=r"(r3) : "r"(a))

#define MMA16816H(d, a, b) \
    asm volatile("mma.sync.aligned.m16n8k16.row.col.f16.f16.f16.f16 " \
        "{%0,%1}, {%2,%3,%4,%5}, {%6,%7}, {%0,%1};" \
        : "+r"((d)[0]), "+r"((d)[1]) \
        : "r"((a)[0]), "r"((a)[1]), "r"((a)[2]), "r"((a)[3]), "r"((b)[0]), "r"((b)[1]))

// SMEM layout (bytes), stride 272:
// A 128x272 | B0 64x272 | B1 64x272 | cnt 512 | cbn2(f16x2) 2048
#define A_OFF    0
#define B_OFF    34816
#define B_STRIDE 17408
#define CN_OFF   69632
#define CB2_OFF  70144
#define SMEM_SZ  72192

// ---------------------------------------------------------------------------
__global__ void k_nop() {}

// ---------------------------------------------------------------------------
// Prep: codebook -> f16 rows + norms. One warp per code.
// ---------------------------------------------------------------------------
__global__ void k_prep(const float* __restrict__ cb) {
    int warp = threadIdx.x >> 5, lane = threadIdx.x & 31;
    int k = (blockIdx.x << 3) + warp;
    float4 v = reinterpret_cast<const float4*>(cb)[k * 32 + lane];
    float n = v.x * v.x + v.y * v.y + v.z * v.z + v.w * v.w;
#pragma unroll
    for (int o = 16; o; o >>= 1) n += __shfl_xor_sync(0xffffffffu, n, o);
    uint2* row = reinterpret_cast<uint2*>(Eb) + (size_t)k * 32;
    uint2 w; w.x = h2u(v.x, v.y); w.y = h2u(v.z, v.w);
    row[lane] = w;
    if (lane == 0) g_cbnorm[k] = n;
}

// ---------------------------------------------------------------------------
// GEMM + threshold emission. CTA = 128 tokens x 1024 codes, 16 chunks of 64.
// 8 warps, each owns 16 tokens x all 64 codes. A fragments register-resident;
// B fragments double-buffered in registers (LDSM k+1 under MMA k).
// ---------------------------------------------------------------------------
__global__ __launch_bounds__(256, 2)
void k_gemm(const float* __restrict__ x) {
    extern __shared__ char smc[];
    const uint32_t sb = smem_u32(smc);
    uint32_t* cnt  = reinterpret_cast<uint32_t*>(smc + CN_OFF);   // 128
    uint32_t* cb2t = reinterpret_cast<uint32_t*>(smc + CB2_OFF);  // 512 f16x2 of cbn/2
    const int tid = threadIdx.x, warp = tid >> 5, lane = tid & 31;
    const int lg = lane >> 2;
    const int tok0 = blockIdx.x << 7;

    if (tid < 128) cnt[tid] = 0u;
#pragma unroll
    for (int i = 0; i < 2; i++) {
        int p = tid + i * 256;
        cb2t[p] = h2u(0.5f * g_cbnorm[2 * p], 0.5f * g_cbnorm[2 * p + 1]);
    }

    // Build A: 128 rows x 128 f16 (272B stride). Thread: row tid/2, half tid&1.
    {
        int r = tid >> 1, h = tid & 1;
        const float4* xr = reinterpret_cast<const float4*>(x + (size_t)(tok0 + r) * 128 + h * 64);
        char* dst = smc + r * 272 + h * 128;
#pragma unroll
        for (int i = 0; i < 8; i++) {
            float4 a = xr[i * 2], b = xr[i * 2 + 1];
            uint4 u;
            u.x = h2u(a.x, a.y); u.y = h2u(a.z, a.w);
            u.z = h2u(b.x, b.y); u.w = h2u(b.z, b.w);
            *reinterpret_cast<uint4*>(dst + i * 16) = u;
        }
    }

    // prefetch chunk 0 (64 rows x 256B = 1024 x 16B, 4/thread)
    {
        const char* src = reinterpret_cast<const char*>(Eb);
        uint32_t bs = sb + B_OFF;
#pragma unroll
        for (int j = 0; j < 4; j++) {
            int e = tid + j * 256;
            CP_ASYNC16(bs + (e >> 4) * 272 + (e & 15) * 16, src + e * 16);
        }
        CP_COMMIT();
    }
    __syncthreads();   // A tile visible for ldmatrix

    // A fragments: register-resident for the whole kernel
    uint32_t areg[8][4];
    {
        const uint32_t aAddr0 = sb + (warp * 16 + (lane & 15)) * 272 + (lane >> 4) * 16;
#pragma unroll
        for (int k = 0; k < 8; k++)
            LDSM4(areg[k][0], areg[k][1], areg[k][2], areg[k][3], aAddr0 + k * 32);
    }

    const uint32_t bBase0 = (((lane >> 4) << 3) + (lane & 7)) * 272 + ((lane >> 3) & 1) * 16;
    float vreg0 = __int_as_float(0xff800000);
    float vreg1 = __int_as_float(0xff800000);

    for (int c = 0; c < NCH; c++) {
        CP_WAIT0();        // chunk c resident
        __syncthreads();   // all warps past reads of the other buffer
        if (c + 1 < NCH) { // prefetch AFTER barrier: race-free with 2 buffers
            const char* src = reinterpret_cast<const char*>(Eb) + (size_t)(c + 1) * 16384;
            uint32_t bs = sb + B_OFF + ((c + 1) & 1) * B_STRIDE;
#pragma unroll
            for (int j = 0; j < 4; j++) {
                int e = tid + j * 256;
                CP_ASYNC16(bs + (e >> 4) * 272 + (e & 15) * 16, src + e * 16);
            }
            CP_COMMIT();
        }

        const uint32_t Bb = sb + B_OFF + (c & 1) * B_STRIDE + bBase0;
        uint32_t acc[8][2];
#pragma unroll
        for (int s = 0; s < 8; s++) { acc[s][0] = 0u; acc[s][1] = 0u; }

        // register double-buffered B fragments
        uint32_t breg[2][4][4];
#pragma unroll
        for (int g = 0; g < 4; g++)
            LDSM4(breg[0][g][0], breg[0][g][1], breg[0][g][2], breg[0][g][3],
                  Bb + g * 16 * 272);
#pragma unroll
        for (int k = 0; k < 8; k++) {
            const int cur = k & 1, nxt = cur ^ 1;
            if (k < 7) {
#pragma unroll
                for (int g = 0; g < 4; g++)
                    LDSM4(breg[nxt][g][0], breg[nxt][g][1], breg[nxt][g][2], breg[nxt][g][3],
                          Bb + g * 16 * 272 + (k + 1) * 32);
            }
#pragma unroll
            for (int g = 0; g < 4; g++) {
                MMA16816H(acc[g * 2],     areg[k], (&breg[cur][g][0]));
                MMA16816H(acc[g * 2 + 1], areg[k], (&breg[cur][g][2]));
            }
        }

        // cbn/2 pairs for this thread's 8 n8-groups
        __half2 cb2[8];
        {
            int pb = c * 32 + (lane & 3);
#pragma unroll
            for (int s = 0; s < 8; s++)
                cb2[s] = *reinterpret_cast<__half2*>(&cb2t[pb + s * 4]);
        }

        // phase 1 (registers only): fold chunk c into running per-token max
#pragma unroll
        for (int dd = 0; dd < 2; dd++) {
            __half2 m01 = __hmax2(
                __hmax2(__hsub2(*reinterpret_cast<__half2*>(&acc[0][dd]), cb2[0]),
                        __hsub2(*reinterpret_cast<__half2*>(&acc[1][dd]), cb2[1])),
                __hmax2(__hsub2(*reinterpret_cast<__half2*>(&acc[2][dd]), cb2[2]),
                        __hsub2(*reinterpret_cast<__half2*>(&acc[3][dd]), cb2[3])));
            __half2 m23 = __hmax2(
                __hmax2(__hsub2(*reinterpret_cast<__half2*>(&acc[4][dd]), cb2[4]),
                        __hsub2(*reinterpret_cast<__half2*>(&acc[5][dd]), cb2[5])),
                __hmax2(__hsub2(*reinterpret_cast<__half2*>(&acc[6][dd]), cb2[6]),
                        __hsub2(*reinterpret_cast<__half2*>(&acc[7][dd]), cb2[7])));
            __half2 mm = __hmax2(m01, m23);
            float m = __half2float(__hmax(__low2half(mm), __high2half(mm)));
            m = fmaxf(m, __shfl_xor_sync(0xffffffffu, m, 1));
            m = fmaxf(m, __shfl_xor_sync(0xffffffffu, m, 2));   // quad max
            if (dd == 0) vreg0 = fmaxf(vreg0, m); else vreg1 = fmaxf(vreg1, m);
        }

        // phase 2: scan & emit (threshold includes current chunk)
        __half2 thr2[2];
        thr2[0] = __half2half2(__float2half_rd(vreg0 - MARGIN));
        thr2[1] = __half2half2(__float2half_rd(vreg1 - MARGIN));
#pragma unroll
        for (int dd = 0; dd < 2; dd++)
#pragma unroll
            for (int s = 0; s < 8; s++) {
                uint32_t mask = __hgt2_mask(
                    *reinterpret_cast<__half2*>(&acc[s][dd]),
                    __hadd2(thr2[dd], cb2[s]));
                if (mask) {
                    int tl = warp * 16 + lg + dd * 8;
                    int code = c * 64 + s * 8 + ((lane & 3) << 1);
                    if (mask & 0xffffu) {
                        uint32_t p = atomicAdd(&cnt[tl], 1u);
                        if (p < CAP) g_list[(size_t)(tok0 + tl) * CAP + p] = (uint16_t)code;
                    }
                    if (mask >> 16) {
                        uint32_t p = atomicAdd(&cnt[tl], 1u);
                        if (p < CAP) g_list[(size_t)(tok0 + tl) * CAP + p] = (uint16_t)(code + 1);
                    }
                }
            }
    }

    __syncthreads();
    if (tid < 128) {
        uint32_t n = cnt[tid];
        g_cnt[tok0 + tid] = (n > CAP) ? CAP : n;
    }
}

// ---------------------------------------------------------------------------
// Rescore (exact fp32) + gather + fused group loss. DRAM-bound (~268MB).
// ---------------------------------------------------------------------------
__global__ __launch_bounds__(1024)
void k_rescore(const float* __restrict__ x, const float* __restrict__ cb,
               float* __restrict__ xq, float* __restrict__ loss) {
    const int g = blockIdx.x;
    const int warp = threadIdx.x >> 5, lane = threadIdx.x & 31;
    __shared__ float ws[32];
    float wacc = 0.0f;

    for (int i = 0; i < 4; i++) {
        int t = g * 128 + warp * 4 + i;
        int n = (int)g_cnt[t];
        float4 x4 = reinterpret_cast<const float4*>(x)[(size_t)t * 32 + lane];
        float bs = __int_as_float(0xff800000);
        int bi = 0x7fffffff;
        float4 be = x4;
        for (int j = 0; j < n; j++) {
            int ij = (int)g_list[(size_t)t * CAP + j];
            float4 e4 = reinterpret_cast<const float4*>(cb)[(size_t)ij * 32 + lane];
            float p = x4.x * e4.x + x4.y * e4.y + x4.z * e4.z + x4.w * e4.w;
#pragma unroll
            for (int o = 16; o; o >>= 1) p += __shfl_xor_sync(0xffffffffu, p, o);
            float s = p - 0.5f * g_cbnorm[ij];
            if (s > bs || (s == bs && ij < bi)) { bs = s; bi = ij; be = e4; }
        }
        float4 q4;
        q4.x = x4.x + (be.x - x4.x);
        q4.y = x4.y + (be.y - x4.y);
        q4.z = x4.z + (be.z - x4.z);
        q4.w = x4.w + (be.w - x4.w);
        reinterpret_cast<float4*>(xq)[(size_t)t * 32 + lane] = q4;
        float d0 = q4.x - x4.x, d1 = q4.y - x4.y, d2 = q4.z - x4.z, d3 = q4.w - x4.w;
        float tl = d0 * d0 + d1 * d1 + d2 * d2 + d3 * d3;
#pragma unroll
        for (int o = 16; o; o >>= 1) tl += __shfl_xor_sync(0xffffffffu, tl, o);
        if (lane == 0) wacc += tl;
    }
    if (lane == 0) ws[warp] = wacc;
    __syncthreads();
    if (threadIdx.x == 0) {
        float s = 0.0f;
#pragma unroll
        for (int w = 0; w < 32; w++) s += ws[w];
        loss[g] = s * (1.25f / 16384.0f);
    }
}

// ---------------------------------------------------------------------------
extern "C" void kernel_launch(void* const* d_in, const int* in_sizes, int n_in,
                              void* d_out, int out_size) {
    const float* x  = (const float*)d_in[0];
    const float* cb = (const float*)d_in[1];
    float* xq = (float*)d_out;
    float* loss;
    if (out_size >= TT * DD + GROUPS) {
        loss = xq + (size_t)TT * DD;
    } else {
        void* p = nullptr;
        cudaGetSymbolAddress(&p, g_loss_dummy);
        loss = (float*)p;
    }
    cudaFuncSetAttribute(k_gemm, cudaFuncAttributeMaxDynamicSharedMemorySize, SMEM_SZ);
    k_prep<<<KK / 8, 256>>>(cb);
    k_nop<<<1, 32>>>();
    k_nop<<<1, 32>>>();          // launch #4 = k_gemm (ncu target)
    k_gemm<<<TT / 128, 256, SMEM_SZ>>>(x);
    k_rescore<<<GROUPS, 1024>>>(x, cb, xq, loss);
}